// round 1
// baseline (speedup 1.0000x reference)
#include <cuda_runtime.h>
#include <math.h>
#include <stdint.h>

// Pairwise negative Euclidean distance via GEMM expansion:
//   out[n][m] = -sqrt(max(||a_n||^2 + ||b_m||^2 - 2 * <a_n, b_m>, 0))
// A = z_anc [N,128] fp32 row-major, B = z_pos_neg [M,128] fp32 row-major.
//
// Round 0: register-blocked fp32 SGEMM (128x128 block tile, 8x8 per thread)
// with fused norm + sqrt epilogue. FFMA-roofline bound (~34 TF/s fp32).

#define TILE 128
#define TK   8
#define DDIM 128

// Scratch for row norms (allocation-free: __device__ globals).
__device__ float g_a2[8192];
__device__ float g_b2[8192];

// One warp per row: sum of squares over D=128 (32 lanes x float4).
__global__ void norms_kernel(const float* __restrict__ A,
                             const float* __restrict__ B,
                             int N, int M) {
    int row  = blockIdx.x * 8 + (threadIdx.x >> 5);
    int lane = threadIdx.x & 31;

    const float* src;
    float* dst;
    if (row < N) {
        src = A + (size_t)row * DDIM;
        dst = g_a2 + row;
    } else {
        int r = row - N;
        if (r >= M) return;
        src = B + (size_t)r * DDIM;
        dst = g_b2 + r;
    }

    float4 v = reinterpret_cast<const float4*>(src)[lane];
    float s = v.x * v.x + v.y * v.y + v.z * v.z + v.w * v.w;
    #pragma unroll
    for (int o = 16; o; o >>= 1)
        s += __shfl_xor_sync(0xffffffffu, s, o);
    if (lane == 0) *dst = s;
}

__global__ __launch_bounds__(256, 2)
void dist_kernel(const float* __restrict__ A,
                 const float* __restrict__ B,
                 float* __restrict__ out,
                 int N, int M) {
    __shared__ float As[TK][TILE];
    __shared__ float Bs[TK][TILE];

    const int tid = threadIdx.x;
    const int n0 = blockIdx.y * TILE;
    const int m0 = blockIdx.x * TILE;

    // Global-load mapping: thread t loads one float4 per tile per chunk.
    // rowL = t/2 (0..127), kp = (t&1)*4 -> fully coalesced 128B segments.
    const int rowL = tid >> 1;
    const int kp   = (tid & 1) * 4;

    const float4* Aload =
        reinterpret_cast<const float4*>(A + (size_t)(n0 + rowL) * DDIM + kp);
    const float4* Bload =
        reinterpret_cast<const float4*>(B + (size_t)(m0 + rowL) * DDIM + kp);

    // Compute mapping: 16x16 thread grid, each thread owns 8 rows x 8 cols.
    const int tx = tid & 15;   // col group
    const int ty = tid >> 4;   // row group

    float acc[8][8];
    #pragma unroll
    for (int i = 0; i < 8; i++)
        #pragma unroll
        for (int j = 0; j < 8; j++)
            acc[i][j] = 0.0f;

    // Prefetch chunk 0 into registers.
    float4 aReg = Aload[0];
    float4 bReg = Bload[0];

    #pragma unroll 1
    for (int c = 0; c < DDIM / TK; c++) {
        // Commit prefetched chunk to smem, transposed [k][row].
        As[kp + 0][rowL] = aReg.x;
        As[kp + 1][rowL] = aReg.y;
        As[kp + 2][rowL] = aReg.z;
        As[kp + 3][rowL] = aReg.w;
        Bs[kp + 0][rowL] = bReg.x;
        Bs[kp + 1][rowL] = bReg.y;
        Bs[kp + 2][rowL] = bReg.z;
        Bs[kp + 3][rowL] = bReg.w;
        __syncthreads();

        // Prefetch next chunk (overlaps with FMA work below).
        if (c < DDIM / TK - 1) {
            aReg = Aload[(c + 1) * 2];   // +8 floats along K per chunk
            bReg = Bload[(c + 1) * 2];
        }

        #pragma unroll
        for (int k = 0; k < TK; k++) {
            float a[8], b[8];
            *reinterpret_cast<float4*>(&a[0]) =
                *reinterpret_cast<const float4*>(&As[k][ty * 8]);
            *reinterpret_cast<float4*>(&a[4]) =
                *reinterpret_cast<const float4*>(&As[k][ty * 8 + 4]);
            *reinterpret_cast<float4*>(&b[0]) =
                *reinterpret_cast<const float4*>(&Bs[k][tx * 8]);
            *reinterpret_cast<float4*>(&b[4]) =
                *reinterpret_cast<const float4*>(&Bs[k][tx * 8 + 4]);

            #pragma unroll
            for (int i = 0; i < 8; i++)
                #pragma unroll
                for (int j = 0; j < 8; j++)
                    acc[i][j] = fmaf(a[i], b[j], acc[i][j]);
        }
        __syncthreads();
    }

    // Fused epilogue: -sqrt(max(a2 + b2 - 2*ab, 0)), coalesced float4 stores.
    float a2v[8], b2v[8];
    #pragma unroll
    for (int i = 0; i < 8; i++) a2v[i] = g_a2[n0 + ty * 8 + i];
    #pragma unroll
    for (int j = 0; j < 8; j++) b2v[j] = g_b2[m0 + tx * 8 + j];

    #pragma unroll
    for (int i = 0; i < 8; i++) {
        float vals[8];
        #pragma unroll
        for (int j = 0; j < 8; j++) {
            float d2 = fmaf(-2.0f, acc[i][j], a2v[i] + b2v[j]);
            d2 = fmaxf(d2, 0.0f);
            vals[j] = -sqrtf(d2);
        }
        float* orow = out + (size_t)(n0 + ty * 8 + i) * M + (m0 + tx * 8);
        reinterpret_cast<float4*>(orow)[0] =
            make_float4(vals[0], vals[1], vals[2], vals[3]);
        reinterpret_cast<float4*>(orow)[1] =
            make_float4(vals[4], vals[5], vals[6], vals[7]);
    }
}

extern "C" void kernel_launch(void* const* d_in, const int* in_sizes, int n_in,
                              void* d_out, int out_size) {
    const float* A = (const float*)d_in[0];   // z_anc [N,128]
    const float* B = (const float*)d_in[1];   // z_pos_neg [M,128]
    float* out = (float*)d_out;               // [N, M]

    const int D = DDIM;
    const int N = in_sizes[0] / D;
    const int M = in_sizes[1] / D;

    // 1) Row norms (one warp per row).
    int totalRows = N + M;
    norms_kernel<<<(totalRows + 7) / 8, 256>>>(A, B, N, M);

    // 2) Tiled GEMM + fused distance epilogue.
    dim3 grid(M / TILE, N / TILE);
    dist_kernel<<<grid, 256>>>(A, B, out, N, M);
}

// round 3
// speedup vs baseline: 2.6528x; 2.6528x over previous
#include <cuda_runtime.h>
#include <math.h>
#include <stdint.h>

// out[n][m] = -sqrt(max(||a_n||^2 + ||b_m||^2 - 2 <a_n,b_m>, 0))
// Round 2: portable tensor-core path. The harness builds PTX at compute_103
// (no 'a' suffix) so tcgen05/TMEM are unavailable; use mma.sync tf32
// (m16n8k8) instead. CTA 128x128 tile, full K=128 resident in swizzled smem,
// 8 warps x (2x8) mma tiles, double-buffered fragment loads, FFMA-only sqrt.

#define DDIM 128
#define TM   128
#define TN   128

__device__ float g_a2[8192];
__device__ float g_b2[8192];

// ---------------- norms: one warp per row ----------------
__global__ void norms_kernel(const float* __restrict__ A,
                             const float* __restrict__ B, int N, int M) {
    int row  = blockIdx.x * 8 + (threadIdx.x >> 5);
    int lane = threadIdx.x & 31;
    const float* src;
    float* dst;
    if (row < N) { src = A + (size_t)row * DDIM; dst = g_a2 + row; }
    else {
        int r = row - N;
        if (r >= M) return;
        src = B + (size_t)r * DDIM; dst = g_b2 + r;
    }
    float4 v = reinterpret_cast<const float4*>(src)[lane];
    float s = v.x * v.x + v.y * v.y + v.z * v.z + v.w * v.w;
    #pragma unroll
    for (int o = 16; o; o >>= 1) s += __shfl_xor_sync(0xffffffffu, s, o);
    if (lane == 0) *dst = s;
}

// tf32 mma m16n8k8: D(16x8) += A(16x8) * B(8x8)
__device__ __forceinline__ void mma_tf32(float* c, const uint32_t* a,
                                         const uint32_t* b) {
    asm volatile(
        "mma.sync.aligned.m16n8k8.row.col.f32.tf32.tf32.f32 "
        "{%0,%1,%2,%3}, {%4,%5,%6,%7}, {%8,%9}, {%0,%1,%2,%3};"
        : "+f"(c[0]), "+f"(c[1]), "+f"(c[2]), "+f"(c[3])
        : "r"(a[0]), "r"(a[1]), "r"(a[2]), "r"(a[3]), "r"(b[0]), "r"(b[1]));
}

// FFMA-only sqrt: bit-trick rsqrt + 2 Newton steps, then x*rsqrt(x).
// x==0 -> y finite huge -> 0*y == 0 (no NaN).
__device__ __forceinline__ float fast_sqrt(float x) {
    float y = __int_as_float(0x5f3759df - (__float_as_int(x) >> 1));
    float h = 0.5f * x;
    y = y * (1.5f - h * y * y);
    y = y * (1.5f - h * y * y);
    return x * y;
}

// smem: As[128*128] | Bs[128*128] | a2s[128] | b2s[128]  (floats)
#define AS_OFF   0
#define BS_OFF   16384
#define A2S_OFF  32768
#define B2S_OFF  32896
#define SMEM_FLOATS (33024)
#define SMEM_BYTES  (SMEM_FLOATS * 4)

// swizzled float index for element (row, k) in a [128][128] tile
__device__ __forceinline__ int sw_idx(int row, int k) {
    return row * 128 + (k ^ ((row & 7) << 2));
}

__global__ __launch_bounds__(256, 1)
void dist_mma_kernel(const float* __restrict__ A, const float* __restrict__ B,
                     float* __restrict__ out, int N, int M) {
    extern __shared__ float smem[];
    float* As  = smem + AS_OFF;
    float* Bs  = smem + BS_OFF;
    float* a2s = smem + A2S_OFF;
    float* b2s = smem + B2S_OFF;

    const int tid  = threadIdx.x;
    const int wid  = tid >> 5;
    const int lane = tid & 31;
    const int g    = lane >> 2;   // groupID
    const int tig  = lane & 3;    // threadID in group
    const int row0 = blockIdx.y * TM;   // output rows (A rows)
    const int col0 = blockIdx.x * TN;   // output cols (B rows)

    // ---- load tiles (float4 coalesced GMEM -> swizzled smem) ----
    const float4* Ag = reinterpret_cast<const float4*>(A + (size_t)row0 * DDIM);
    const float4* Bg = reinterpret_cast<const float4*>(B + (size_t)col0 * DDIM);
    #pragma unroll
    for (int it = 0; it < 16; it++) {
        int f = tid + it * 256;          // 0..4095 float4s
        int r = f >> 5, kq = f & 31;     // row, float4-within-row
        int k0 = kq * 4;
        int idx = r * 128 + (k0 ^ ((r & 7) << 2));  // 4-aligned after xor
        *reinterpret_cast<float4*>(&As[idx]) = Ag[f];
        *reinterpret_cast<float4*>(&Bs[idx]) = Bg[f];
    }
    if (tid < 128) a2s[tid] = g_a2[row0 + tid];
    else           b2s[tid - 128] = g_b2[col0 + tid - 128];
    __syncthreads();

    // ---- warp tiling: 4 (m) x 2 (n); warp tile 32 x 64 ----
    const int m_base = (wid & 3) * 32;
    const int n_base = (wid >> 2) * 64;

    const uint32_t* Asu = reinterpret_cast<const uint32_t*>(As);
    const uint32_t* Bsu = reinterpret_cast<const uint32_t*>(Bs);
    const int xc = g << 2;  // xor const: all fragment rows have (row&7)==g

    // Per-thread fragment row bases (float index of row start)
    int aRow[2][2], bRow[8];
    #pragma unroll
    for (int mt = 0; mt < 2; mt++) {
        aRow[mt][0] = (m_base + mt * 16 + g) * 128;
        aRow[mt][1] = (m_base + mt * 16 + g + 8) * 128;
    }
    #pragma unroll
    for (int nt = 0; nt < 8; nt++)
        bRow[nt] = (n_base + nt * 8 + g) * 128;

    float acc[2][8][4];
    #pragma unroll
    for (int mt = 0; mt < 2; mt++)
        #pragma unroll
        for (int nt = 0; nt < 8; nt++)
            #pragma unroll
            for (int e = 0; e < 4; e++) acc[mt][nt][e] = 0.0f;

    uint32_t af[2][2][4], bf[2][8][2];

    // fragment load for k-step ks into buffer bufsel
    #define LOAD_FRAGS(ks, buf)                                              \
        do {                                                                 \
            int kA = ((ks) * 8 + tig) ^ xc;                                  \
            int kB = ((ks) * 8 + tig + 4) ^ xc;                              \
            _Pragma("unroll")                                                \
            for (int mt = 0; mt < 2; mt++) {                                 \
                af[buf][mt][0] = Asu[aRow[mt][0] + kA];                      \
                af[buf][mt][1] = Asu[aRow[mt][1] + kA];                      \
                af[buf][mt][2] = Asu[aRow[mt][0] + kB];                      \
                af[buf][mt][3] = Asu[aRow[mt][1] + kB];                      \
            }                                                                \
            _Pragma("unroll")                                                \
            for (int nt = 0; nt < 8; nt++) {                                 \
                bf[buf][nt][0] = Bsu[bRow[nt] + kA];                         \
                bf[buf][nt][1] = Bsu[bRow[nt] + kB];                         \
            }                                                                \
        } while (0)

    LOAD_FRAGS(0, 0);
    int cur = 0;
    #pragma unroll
    for (int ks = 0; ks < 16; ks++) {
        int nxt = cur ^ 1;
        if (ks < 15) LOAD_FRAGS(ks + 1, nxt);
        #pragma unroll
        for (int mt = 0; mt < 2; mt++)
            #pragma unroll
            for (int nt = 0; nt < 8; nt++)
                mma_tf32(acc[mt][nt], af[cur][mt], bf[cur][nt]);
        cur = nxt;
    }
    #undef LOAD_FRAGS

    // ---- fused epilogue ----
    // C frag: c0 (row g, col 2*tig), c1 (+1), c2 (row g+8), c3 (+1)
    float a2v[2][2];
    #pragma unroll
    for (int mt = 0; mt < 2; mt++) {
        a2v[mt][0] = a2s[m_base + mt * 16 + g];
        a2v[mt][1] = a2s[m_base + mt * 16 + g + 8];
    }

    #pragma unroll
    for (int mt = 0; mt < 2; mt++) {
        #pragma unroll
        for (int nt = 0; nt < 8; nt++) {
            int c = n_base + nt * 8 + tig * 2;
            float b20 = b2s[c], b21 = b2s[c + 1];
            float d00 = fmaxf(fmaf(-2.0f, acc[mt][nt][0], a2v[mt][0] + b20), 0.0f);
            float d01 = fmaxf(fmaf(-2.0f, acc[mt][nt][1], a2v[mt][0] + b21), 0.0f);
            float d10 = fmaxf(fmaf(-2.0f, acc[mt][nt][2], a2v[mt][1] + b20), 0.0f);
            float d11 = fmaxf(fmaf(-2.0f, acc[mt][nt][3], a2v[mt][1] + b21), 0.0f);
            float2 v0 = make_float2(-fast_sqrt(d00), -fast_sqrt(d01));
            float2 v1 = make_float2(-fast_sqrt(d10), -fast_sqrt(d11));
            size_t o0 = (size_t)(row0 + m_base + mt * 16 + g) * M + (col0 + c);
            *reinterpret_cast<float2*>(&out[o0]) = v0;
            *reinterpret_cast<float2*>(&out[o0 + (size_t)8 * M]) = v1;
        }
    }
}

extern "C" void kernel_launch(void* const* d_in, const int* in_sizes, int n_in,
                              void* d_out, int out_size) {
    const float* A = (const float*)d_in[0];   // z_anc [N,128]
    const float* B = (const float*)d_in[1];   // z_pos_neg [M,128]
    float* out = (float*)d_out;

    const int N = in_sizes[0] / DDIM;
    const int M = in_sizes[1] / DDIM;

    // Runs on the (non-captured) correctness call first; capture-safe.
    static bool attr_ok = [] {
        cudaFuncSetAttribute(dist_mma_kernel,
                             cudaFuncAttributeMaxDynamicSharedMemorySize,
                             SMEM_BYTES);
        return true;
    }();
    (void)attr_ok;

    int totalRows = N + M;
    norms_kernel<<<(totalRows + 7) / 8, 256>>>(A, B, N, M);

    dim3 grid(M / TN, N / TM);
    dist_mma_kernel<<<grid, 256, SMEM_BYTES>>>(A, B, out, N, M);
}

// round 4
// speedup vs baseline: 2.8344x; 1.0685x over previous
#include <cuda_runtime.h>
#include <math.h>
#include <stdint.h>

// out[n][m] = -sqrt(max(||a_n||^2 + ||b_m||^2 - 2 <a_n,b_m>, 0))
// Round 4: mma.sync tf32 + ldmatrix fragment feed + 2 CTAs/SM.
//  - CTA tile 128(m) x 64(n), full K=128 in swizzled smem (~97KB -> occ 2).
//  - ldmatrix.m8n8.x4.b16 loads tf32 fragments (8x4 tf32 block == 8x8 b16
//    tile; lane l gets (row l/4, col l%4) == mma fragment layout).
//  - 8 warps in 4(m) x 2(n); warp tile 32x32; 4 LDSM + 8 MMA per k-step.
//  - FFMA-only Newton sqrt epilogue (no MUFU).

#define DDIM 128
#define TM   128
#define TN   64

__device__ float g_a2[8192];
__device__ float g_b2[8192];

// ---------------- norms: one warp per row ----------------
__global__ void norms_kernel(const float* __restrict__ A,
                             const float* __restrict__ B, int N, int M) {
    int row  = blockIdx.x * 8 + (threadIdx.x >> 5);
    int lane = threadIdx.x & 31;
    const float* src;
    float* dst;
    if (row < N) { src = A + (size_t)row * DDIM; dst = g_a2 + row; }
    else {
        int r = row - N;
        if (r >= M) return;
        src = B + (size_t)r * DDIM; dst = g_b2 + r;
    }
    float4 v = reinterpret_cast<const float4*>(src)[lane];
    float s = v.x * v.x + v.y * v.y + v.z * v.z + v.w * v.w;
    #pragma unroll
    for (int o = 16; o; o >>= 1) s += __shfl_xor_sync(0xffffffffu, s, o);
    if (lane == 0) *dst = s;
}

__device__ __forceinline__ uint32_t smem_u32(const void* p) {
    uint32_t a;
    asm("{ .reg .u64 t; cvta.to.shared.u64 t, %1; cvt.u32.u64 %0, t; }"
        : "=r"(a) : "l"(p));
    return a;
}

__device__ __forceinline__ void mma_tf32(float* c, const uint32_t* a,
                                         const uint32_t* b) {
    asm volatile(
        "mma.sync.aligned.m16n8k8.row.col.f32.tf32.tf32.f32 "
        "{%0,%1,%2,%3}, {%4,%5,%6,%7}, {%8,%9}, {%0,%1,%2,%3};"
        : "+f"(c[0]), "+f"(c[1]), "+f"(c[2]), "+f"(c[3])
        : "r"(a[0]), "r"(a[1]), "r"(a[2]), "r"(a[3]), "r"(b[0]), "r"(b[1]));
}

__device__ __forceinline__ void ldsm_x4(uint32_t* r, uint32_t addr) {
    asm volatile(
        "ldmatrix.sync.aligned.m8n8.x4.shared.b16 {%0,%1,%2,%3}, [%4];"
        : "=r"(r[0]), "=r"(r[1]), "=r"(r[2]), "=r"(r[3]) : "r"(addr));
}

// FFMA-only sqrt: magic rsqrt + 2 Newton steps; 0 -> 0 (no NaN).
__device__ __forceinline__ float fast_sqrt(float x) {
    float y = __int_as_float(0x5f3759df - (__float_as_int(x) >> 1));
    float h = 0.5f * x;
    y = y * (1.5f - h * y * y);
    y = y * (1.5f - h * y * y);
    return x * y;
}

// smem floats: As[128*128] | Bs[64*128] | a2s[128] | b2s[64]
#define AS_F    0
#define BS_F    16384
#define A2S_F   24576
#define B2S_F   24704
#define SMEM_FLOATS 24768
#define SMEM_BYTES  (SMEM_FLOATS * 4)

__global__ __launch_bounds__(256, 2)
void dist_mma_kernel(const float* __restrict__ A, const float* __restrict__ B,
                     float* __restrict__ out, int N, int M) {
    extern __shared__ float smem[];
    float* As  = smem + AS_F;
    float* Bs  = smem + BS_F;
    float* a2s = smem + A2S_F;
    float* b2s = smem + B2S_F;

    const int tid  = threadIdx.x;
    const int wid  = tid >> 5;
    const int lane = tid & 31;
    const int g    = lane >> 2;
    const int tig  = lane & 3;
    const int row0 = blockIdx.y * TM;   // A rows
    const int col0 = blockIdx.x * TN;   // B rows

    // ---- GMEM -> swizzled smem (element (r,k) at r*128 + (k ^ ((r&7)<<2))) ----
    const float4* Ag = reinterpret_cast<const float4*>(A + (size_t)row0 * DDIM);
    const float4* Bg = reinterpret_cast<const float4*>(B + (size_t)col0 * DDIM);
    #pragma unroll
    for (int it = 0; it < 16; it++) {
        int f = tid + it * 256;        // 0..4095
        int r = f >> 5, k0 = (f & 31) * 4;
        int idx = r * 128 + (k0 ^ ((r & 7) << 2));
        *reinterpret_cast<float4*>(&As[idx]) = Ag[f];
    }
    #pragma unroll
    for (int it = 0; it < 8; it++) {
        int f = tid + it * 256;        // 0..2047
        int r = f >> 5, k0 = (f & 31) * 4;
        int idx = r * 128 + (k0 ^ ((r & 7) << 2));
        *reinterpret_cast<float4*>(&Bs[idx]) = Bg[f];
    }
    if (tid < 128)       a2s[tid] = g_a2[row0 + tid];
    else if (tid < 192)  b2s[tid - 128] = g_b2[col0 + tid - 128];
    __syncthreads();

    // ---- warp tiling: 4(m) x 2(n); warp tile 32x32 ----
    const int mb = (wid & 3) * 32;
    const int nb = (wid >> 2) * 32;

    const uint32_t AsAddr = smem_u32(As);
    const uint32_t BsAddr = smem_u32(Bs);

    // ldmatrix per-lane row / k-offset assignment.
    // A x4 (per mt): tiles r0..r3 = (rows 0-7,k0)(rows 8-15,k0)(0-7,k0+4)(8-15,k0+4)
    //   lanes 0-15 -> rows 0..15 @ dk=0 ; lanes 16-31 -> rows 0..15 @ dk=4
    const int rA_l  = lane & 15;              // row within 16
    const int dkA   = (lane >> 4) << 2;       // 0 or 4
    // B x4 (per q): tiles = (n 0-7,k0)(n 0-7,k0+4)(n 8-15,k0)(n 8-15,k0+4)
    //   lanes 0-7: rows 0-7 dk0 ; 8-15: rows 0-7 dk4 ; 16-23: rows 8-15 dk0 ;
    //   24-31: rows 8-15 dk4
    const int rB_l  = (lane & 7) + ((lane >> 4) << 3);
    const int dkB   = ((lane >> 3) & 1) << 2;

    // Per-lane bases (byte addresses minus the per-ks xor'd k term)
    uint32_t aBase[2], bBase[2];
    int aXc[2], bXc[2];      // swizzle xor constants (in floats)
    int aDk[2], bDk[2];
    #pragma unroll
    for (int mt = 0; mt < 2; mt++) {
        int r = mb + mt * 16 + rA_l;
        aBase[mt] = AsAddr + r * 512;
        aXc[mt]   = (r & 7) << 2;
        aDk[mt]   = dkA;
    }
    #pragma unroll
    for (int q = 0; q < 2; q++) {
        int r = nb + q * 16 + rB_l;
        bBase[q] = BsAddr + r * 512;
        bXc[q]   = (r & 7) << 2;
        bDk[q]   = dkB;
    }

    float acc[2][4][4];
    #pragma unroll
    for (int mt = 0; mt < 2; mt++)
        #pragma unroll
        for (int nt = 0; nt < 4; nt++)
            #pragma unroll
            for (int e = 0; e < 4; e++) acc[mt][nt][e] = 0.0f;

    uint32_t af[2][2][4];   // [buf][mt][reg]
    uint32_t bf[2][4][2];   // [buf][nt][reg]

    #define LOAD_FRAGS(ks, buf)                                               \
        do {                                                                  \
            int kk = (ks) << 3;                                               \
            _Pragma("unroll")                                                 \
            for (int mt = 0; mt < 2; mt++) {                                  \
                uint32_t ad = aBase[mt] + ((((kk | aDk[mt]) ^ aXc[mt])) << 2);\
                ldsm_x4(af[buf][mt], ad);                                     \
            }                                                                 \
            _Pragma("unroll")                                                 \
            for (int q = 0; q < 2; q++) {                                     \
                uint32_t bd = bBase[q] + ((((kk | bDk[q]) ^ bXc[q])) << 2);   \
                uint32_t t[4];                                                \
                ldsm_x4(t, bd);                                               \
                bf[buf][q * 2 + 0][0] = t[0];                                 \
                bf[buf][q * 2 + 0][1] = t[1];                                 \
                bf[buf][q * 2 + 1][0] = t[2];                                 \
                bf[buf][q * 2 + 1][1] = t[3];                                 \
            }                                                                 \
        } while (0)

    LOAD_FRAGS(0, 0);
    int cur = 0;
    #pragma unroll
    for (int ks = 0; ks < 16; ks++) {
        int nxt = cur ^ 1;
        if (ks < 15) LOAD_FRAGS(ks + 1, nxt);
        #pragma unroll
        for (int mt = 0; mt < 2; mt++)
            #pragma unroll
            for (int nt = 0; nt < 4; nt++)
                mma_tf32(acc[mt][nt], af[cur][mt], bf[cur][nt]);
        cur = nxt;
    }
    #undef LOAD_FRAGS

    // ---- fused epilogue ----
    float a2v[2][2];
    #pragma unroll
    for (int mt = 0; mt < 2; mt++) {
        a2v[mt][0] = a2s[mb + mt * 16 + g];
        a2v[mt][1] = a2s[mb + mt * 16 + g + 8];
    }

    #pragma unroll
    for (int mt = 0; mt < 2; mt++) {
        #pragma unroll
        for (int nt = 0; nt < 4; nt++) {
            int c = nb + nt * 8 + tig * 2;
            float b20 = b2s[c], b21 = b2s[c + 1];
            float d00 = fmaxf(fmaf(-2.0f, acc[mt][nt][0], a2v[mt][0] + b20), 0.0f);
            float d01 = fmaxf(fmaf(-2.0f, acc[mt][nt][1], a2v[mt][0] + b21), 0.0f);
            float d10 = fmaxf(fmaf(-2.0f, acc[mt][nt][2], a2v[mt][1] + b20), 0.0f);
            float d11 = fmaxf(fmaf(-2.0f, acc[mt][nt][3], a2v[mt][1] + b21), 0.0f);
            float2 v0 = make_float2(-fast_sqrt(d00), -fast_sqrt(d01));
            float2 v1 = make_float2(-fast_sqrt(d10), -fast_sqrt(d11));
            size_t o0 = (size_t)(row0 + mb + mt * 16 + g) * M + (col0 + c);
            *reinterpret_cast<float2*>(&out[o0]) = v0;
            *reinterpret_cast<float2*>(&out[o0 + (size_t)8 * M]) = v1;
        }
    }
}

extern "C" void kernel_launch(void* const* d_in, const int* in_sizes, int n_in,
                              void* d_out, int out_size) {
    const float* A = (const float*)d_in[0];   // z_anc [N,128]
    const float* B = (const float*)d_in[1];   // z_pos_neg [M,128]
    float* out = (float*)d_out;

    const int N = in_sizes[0] / DDIM;
    const int M = in_sizes[1] / DDIM;

    // First call is the (non-captured) correctness run; capture-safe.
    static bool attr_ok = [] {
        cudaFuncSetAttribute(dist_mma_kernel,
                             cudaFuncAttributeMaxDynamicSharedMemorySize,
                             SMEM_BYTES);
        return true;
    }();
    (void)attr_ok;

    int totalRows = N + M;
    norms_kernel<<<(totalRows + 7) / 8, 256>>>(A, B, N, M);

    dim3 grid(M / TN, N / TM);
    dist_mma_kernel<<<grid, 256, SMEM_BYTES>>>(A, B, out, N, M);
}

// round 7
// speedup vs baseline: 2.8841x; 1.0175x over previous
#include <cuda_runtime.h>
#include <math.h>
#include <stdint.h>

// out[n][m] = -sqrt(max(||a_n||^2 + ||b_m||^2 - 2 <a_n,b_m>, 0))
// Round 5: raise MAC/byte of the fragment feed (L1 was the binding pipe).
//  - Warp tile 64x32 (4x4 m16n8k8): 16384 MACs per 3072 B LDSM -> 5.33 MAC/B.
//  - 128-thread CTAs (4 warps, 2m x 2n), CTA tile 128x64, full K resident,
//    2 CTAs/SM (smem ~97KB each) for load/compute phase overlap.
//  - ldmatrix.m8n8.x4.b16 fragment loads, double-buffered over k.
//  - FFMA-only Newton sqrt epilogue (no MUFU).

#define DDIM 128
#define TM   128
#define TN   64

__device__ float g_a2[8192];
__device__ float g_b2[8192];

// ---------------- norms: one warp per row ----------------
__global__ void norms_kernel(const float* __restrict__ A,
                             const float* __restrict__ B, int N, int M) {
    int row  = blockIdx.x * 8 + (threadIdx.x >> 5);
    int lane = threadIdx.x & 31;
    const float* src;
    float* dst;
    if (row < N) { src = A + (size_t)row * DDIM; dst = g_a2 + row; }
    else {
        int r = row - N;
        if (r >= M) return;
        src = B + (size_t)r * DDIM; dst = g_b2 + r;
    }
    float4 v = reinterpret_cast<const float4*>(src)[lane];
    float s = v.x * v.x + v.y * v.y + v.z * v.z + v.w * v.w;
    #pragma unroll
    for (int o = 16; o; o >>= 1) s += __shfl_xor_sync(0xffffffffu, s, o);
    if (lane == 0) *dst = s;
}

__device__ __forceinline__ uint32_t smem_u32(const void* p) {
    uint32_t a;
    asm("{ .reg .u64 t; cvta.to.shared.u64 t, %1; cvt.u32.u64 %0, t; }"
        : "=r"(a) : "l"(p));
    return a;
}

__device__ __forceinline__ void mma_tf32(float* c, const uint32_t* a,
                                         const uint32_t* b) {
    asm volatile(
        "mma.sync.aligned.m16n8k8.row.col.f32.tf32.tf32.f32 "
        "{%0,%1,%2,%3}, {%4,%5,%6,%7}, {%8,%9}, {%0,%1,%2,%3};"
        : "+f"(c[0]), "+f"(c[1]), "+f"(c[2]), "+f"(c[3])
        : "r"(a[0]), "r"(a[1]), "r"(a[2]), "r"(a[3]), "r"(b[0]), "r"(b[1]));
}

__device__ __forceinline__ void ldsm_x4(uint32_t* r, uint32_t addr) {
    asm volatile(
        "ldmatrix.sync.aligned.m8n8.x4.shared.b16 {%0,%1,%2,%3}, [%4];"
        : "=r"(r[0]), "=r"(r[1]), "=r"(r[2]), "=r"(r[3]) : "r"(addr));
}

// FFMA-only sqrt: magic rsqrt + 2 Newton steps; 0 -> 0 (no NaN).
__device__ __forceinline__ float fast_sqrt(float x) {
    float y = __int_as_float(0x5f3759df - (__float_as_int(x) >> 1));
    float h = 0.5f * x;
    y = y * (1.5f - h * y * y);
    y = y * (1.5f - h * y * y);
    return x * y;
}

// smem floats: As[128*128] | Bs[64*128] | a2s[128] | b2s[64]
#define AS_F    0
#define BS_F    16384
#define A2S_F   24576
#define B2S_F   24704
#define SMEM_FLOATS 24768
#define SMEM_BYTES  (SMEM_FLOATS * 4)

__global__ __launch_bounds__(128, 2)
void dist_mma_kernel(const float* __restrict__ A, const float* __restrict__ B,
                     float* __restrict__ out, int N, int M) {
    extern __shared__ float smem[];
    float* As  = smem + AS_F;
    float* Bs  = smem + BS_F;
    float* a2s = smem + A2S_F;
    float* b2s = smem + B2S_F;

    const int tid  = threadIdx.x;
    const int wid  = tid >> 5;      // 0..3
    const int lane = tid & 31;
    const int g    = lane >> 2;
    const int tig  = lane & 3;
    const int row0 = blockIdx.y * TM;   // A rows
    const int col0 = blockIdx.x * TN;   // B rows

    // ---- GMEM -> swizzled smem (element (r,k) at r*128 + (k ^ ((r&7)<<2))) ----
    const float4* Ag = reinterpret_cast<const float4*>(A + (size_t)row0 * DDIM);
    const float4* Bg = reinterpret_cast<const float4*>(B + (size_t)col0 * DDIM);
    #pragma unroll
    for (int it = 0; it < 32; it++) {
        int f = tid + it * 128;        // 0..4095
        int r = f >> 5, k0 = (f & 31) * 4;
        int idx = r * 128 + (k0 ^ ((r & 7) << 2));
        *reinterpret_cast<float4*>(&As[idx]) = Ag[f];
    }
    #pragma unroll
    for (int it = 0; it < 16; it++) {
        int f = tid + it * 128;        // 0..2047
        int r = f >> 5, k0 = (f & 31) * 4;
        int idx = r * 128 + (k0 ^ ((r & 7) << 2));
        *reinterpret_cast<float4*>(&Bs[idx]) = Bg[f];
    }
    a2s[tid] = g_a2[row0 + tid];
    if (tid < 64) b2s[tid] = g_b2[col0 + tid];
    __syncthreads();

    // ---- warp tiling: 2(m) x 2(n); warp tile 64x32 ----
    const int mb = (wid & 1) * 64;
    const int nb = (wid >> 1) * 32;

    const uint32_t AsAddr = smem_u32(As);
    const uint32_t BsAddr = smem_u32(Bs);

    // ldmatrix lane mappings (same scheme as round 4):
    // A x4 per mt (16 rows x 8k): lanes 0-15 rows 0..15 @dk0, 16-31 @dk4.
    const int rA_l = lane & 15;
    const int dkA  = (lane >> 4) << 2;
    // B x4 per q (16 n-rows x 8k): tiles (n0-7,k0)(n0-7,k4)(n8-15,k0)(n8-15,k4)
    const int rB_l = (lane & 7) + ((lane >> 4) << 3);
    const int dkB  = ((lane >> 3) & 1) << 2;

    uint32_t aBase[4], bBase[2];
    int aXc[4], bXc[2];
    #pragma unroll
    for (int mt = 0; mt < 4; mt++) {
        int r = mb + mt * 16 + rA_l;
        aBase[mt] = AsAddr + r * 512;
        aXc[mt]   = (r & 7) << 2;
    }
    #pragma unroll
    for (int q = 0; q < 2; q++) {
        int r = nb + q * 16 + rB_l;
        bBase[q] = BsAddr + r * 512;
        bXc[q]   = (r & 7) << 2;
    }

    float acc[4][4][4];
    #pragma unroll
    for (int mt = 0; mt < 4; mt++)
        #pragma unroll
        for (int nt = 0; nt < 4; nt++)
            #pragma unroll
            for (int e = 0; e < 4; e++) acc[mt][nt][e] = 0.0f;

    uint32_t af[2][4][4];   // [buf][mt][reg]
    uint32_t bf[2][4][2];   // [buf][nt][reg]

    #define LOAD_FRAGS(ks, buf)                                               \
        do {                                                                  \
            int kk = (ks) << 3;                                               \
            _Pragma("unroll")                                                 \
            for (int mt = 0; mt < 4; mt++) {                                  \
                uint32_t ad = aBase[mt] + ((((kk | dkA) ^ aXc[mt])) << 2);    \
                ldsm_x4(af[buf][mt], ad);                                     \
            }                                                                 \
            _Pragma("unroll")                                                 \
            for (int q = 0; q < 2; q++) {                                     \
                uint32_t bd = bBase[q] + ((((kk | dkB) ^ bXc[q])) << 2);      \
                uint32_t t[4];                                                \
                ldsm_x4(t, bd);                                               \
                bf[buf][q * 2 + 0][0] = t[0];                                 \
                bf[buf][q * 2 + 0][1] = t[1];                                 \
                bf[buf][q * 2 + 1][0] = t[2];                                 \
                bf[buf][q * 2 + 1][1] = t[3];                                 \
            }                                                                 \
        } while (0)

    LOAD_FRAGS(0, 0);
    int cur = 0;
    #pragma unroll
    for (int ks = 0; ks < 16; ks++) {
        int nxt = cur ^ 1;
        if (ks < 15) LOAD_FRAGS(ks + 1, nxt);
        #pragma unroll
        for (int mt = 0; mt < 4; mt++)
            #pragma unroll
            for (int nt = 0; nt < 4; nt++)
                mma_tf32(acc[mt][nt], af[cur][mt], bf[cur][nt]);
        cur = nxt;
    }
    #undef LOAD_FRAGS

    // ---- fused epilogue ----
    float a2v[4][2];
    #pragma unroll
    for (int mt = 0; mt < 4; mt++) {
        a2v[mt][0] = a2s[mb + mt * 16 + g];
        a2v[mt][1] = a2s[mb + mt * 16 + g + 8];
    }

    #pragma unroll
    for (int mt = 0; mt < 4; mt++) {
        #pragma unroll
        for (int nt = 0; nt < 4; nt++) {
            int c = nb + nt * 8 + tig * 2;
            float b20 = b2s[c], b21 = b2s[c + 1];
            float d00 = fmaxf(fmaf(-2.0f, acc[mt][nt][0], a2v[mt][0] + b20), 0.0f);
            float d01 = fmaxf(fmaf(-2.0f, acc[mt][nt][1], a2v[mt][0] + b21), 0.0f);
            float d10 = fmaxf(fmaf(-2.0f, acc[mt][nt][2], a2v[mt][1] + b20), 0.0f);
            float d11 = fmaxf(fmaf(-2.0f, acc[mt][nt][3], a2v[mt][1] + b21), 0.0f);
            float2 v0 = make_float2(-fast_sqrt(d00), -fast_sqrt(d01));
            float2 v1 = make_float2(-fast_sqrt(d10), -fast_sqrt(d11));
            size_t o0 = (size_t)(row0 + mb + mt * 16 + g) * M + (col0 + c);
            *reinterpret_cast<float2*>(&out[o0]) = v0;
            *reinterpret_cast<float2*>(&out[o0 + (size_t)8 * M]) = v1;
        }
    }
}

extern "C" void kernel_launch(void* const* d_in, const int* in_sizes, int n_in,
                              void* d_out, int out_size) {
    const float* A = (const float*)d_in[0];   // z_anc [N,128]
    const float* B = (const float*)d_in[1];   // z_pos_neg [M,128]
    float* out = (float*)d_out;

    const int N = in_sizes[0] / DDIM;
    const int M = in_sizes[1] / DDIM;

    // First call is the (non-captured) correctness run; capture-safe.
    static bool attr_ok = [] {
        cudaFuncSetAttribute(dist_mma_kernel,
                             cudaFuncAttributeMaxDynamicSharedMemorySize,
                             SMEM_BYTES);
        return true;
    }();
    (void)attr_ok;

    int totalRows = N + M;
    norms_kernel<<<(totalRows + 7) / 8, 256>>>(A, B, N, M);

    dim3 grid(M / TN, N / TM);
    dist_mma_kernel<<<grid, 128, SMEM_BYTES>>>(A, B, out, N, M);
}

// round 8
// speedup vs baseline: 3.2328x; 1.1209x over previous
#include <cuda_runtime.h>
#include <math.h>
#include <stdint.h>

// out[n][m] = -sqrt(max(||a_n||^2 + ||b_m||^2 - 2 <a_n,b_m>, 0))
// Round 8: cut L1 wavefronts on all three streams.
//  - CTA tile 128x256, 8 warps (2m x 4n), warp tile 64x64 -> 8 MAC/B LDSM.
//  - cp.async K-split (2 stages of K=64): load overlaps MMA, no STS pass.
//  - Epilogue staged through smem (conflict-free) -> coalesced STG.128.

#define DDIM 128
#define TM   128
#define TN   256

__device__ float g_a2[8192];
__device__ float g_b2[8192];

__global__ void norms_kernel(const float* __restrict__ A,
                             const float* __restrict__ B, int N, int M) {
    int row  = blockIdx.x * 8 + (threadIdx.x >> 5);
    int lane = threadIdx.x & 31;
    const float* src;
    float* dst;
    if (row < N) { src = A + (size_t)row * DDIM; dst = g_a2 + row; }
    else {
        int r = row - N;
        if (r >= M) return;
        src = B + (size_t)r * DDIM; dst = g_b2 + r;
    }
    float4 v = reinterpret_cast<const float4*>(src)[lane];
    float s = v.x * v.x + v.y * v.y + v.z * v.z + v.w * v.w;
    #pragma unroll
    for (int o = 16; o; o >>= 1) s += __shfl_xor_sync(0xffffffffu, s, o);
    if (lane == 0) *dst = s;
}

__device__ __forceinline__ uint32_t smem_u32(const void* p) {
    uint32_t a;
    asm("{ .reg .u64 t; cvta.to.shared.u64 t, %1; cvt.u32.u64 %0, t; }"
        : "=r"(a) : "l"(p));
    return a;
}
__device__ __forceinline__ void mma_tf32(float* c, const uint32_t* a,
                                         const uint32_t* b) {
    asm volatile(
        "mma.sync.aligned.m16n8k8.row.col.f32.tf32.tf32.f32 "
        "{%0,%1,%2,%3}, {%4,%5,%6,%7}, {%8,%9}, {%0,%1,%2,%3};"
        : "+f"(c[0]), "+f"(c[1]), "+f"(c[2]), "+f"(c[3])
        : "r"(a[0]), "r"(a[1]), "r"(a[2]), "r"(a[3]), "r"(b[0]), "r"(b[1]));
}
__device__ __forceinline__ void ldsm_x4(uint32_t* r, uint32_t addr) {
    asm volatile(
        "ldmatrix.sync.aligned.m8n8.x4.shared.b16 {%0,%1,%2,%3}, [%4];"
        : "=r"(r[0]), "=r"(r[1]), "=r"(r[2]), "=r"(r[3]) : "r"(addr));
}
__device__ __forceinline__ void cp_async16(uint32_t dst, const void* src) {
    asm volatile("cp.async.cg.shared.global [%0], [%1], 16;"
                 :: "r"(dst), "l"(src));
}
#define CP_COMMIT() asm volatile("cp.async.commit_group;" ::: "memory")
#define CP_WAIT(n)  asm volatile("cp.async.wait_group %0;" :: "n"(n) : "memory")

// FFMA-only sqrt: magic rsqrt + 2 Newton steps; 0 -> 0 (no NaN).
__device__ __forceinline__ float fast_sqrt(float x) {
    float y = __int_as_float(0x5f3759df - (__float_as_int(x) >> 1));
    float h = 0.5f * x;
    y = y * (1.5f - h * y * y);
    y = y * (1.5f - h * y * y);
    return x * y;
}

// smem floats: As[128*128] | Bs[256*128] | a2s[128] | b2s[256]
#define AS_F    0
#define BS_F    16384
#define A2S_F   49152
#define B2S_F   49280
#define SMEM_FLOATS 49536
#define SMEM_BYTES  (SMEM_FLOATS * 4)
#define STG_STRIDE  72   // stage stride (mod 32 = 8; + xor4 -> conflict-free)

__global__ __launch_bounds__(256, 1)
void dist_mma_kernel(const float* __restrict__ A, const float* __restrict__ B,
                     float* __restrict__ out, int N, int M) {
    extern __shared__ float smem[];
    float* a2s = smem + A2S_F;
    float* b2s = smem + B2S_F;

    const int tid  = threadIdx.x;
    const int wid  = tid >> 5;      // 0..7
    const int lane = tid & 31;
    const int g    = lane >> 2;
    const int tig  = lane & 3;
    const int row0 = blockIdx.y * TM;   // A rows
    const int col0 = blockIdx.x * TN;   // B rows

    const uint32_t AsA = smem_u32(smem + AS_F);
    const uint32_t BsA = smem_u32(smem + BS_F);

    // norms into smem
    if (tid < 128) a2s[tid] = g_a2[row0 + tid];
    b2s[tid] = g_b2[col0 + tid];

    // ---- cp.async: two K-stages (K 0..63, 64..127), swizzled dst ----
    const float4* Ag = reinterpret_cast<const float4*>(A + (size_t)row0 * DDIM);
    const float4* Bg = reinterpret_cast<const float4*>(B + (size_t)col0 * DDIM);
    #pragma unroll
    for (int s = 0; s < 2; s++) {
        #pragma unroll
        for (int i = 0; i < 8; i++) {               // A: 2048 f4 per stage
            int f = tid + i * 256;
            int r = f >> 4, kq = f & 15;
            int kf = s * 16 + kq;                   // float4 col in row
            int idx = r * 128 + ((kf * 4) ^ ((r & 7) << 2));
            cp_async16(AsA + idx * 4, Ag + (size_t)r * 32 + kf);
        }
        #pragma unroll
        for (int i = 0; i < 16; i++) {              // B: 4096 f4 per stage
            int f = tid + i * 256;
            int r = f >> 4, kq = f & 15;
            int kf = s * 16 + kq;
            int idx = r * 128 + ((kf * 4) ^ ((r & 7) << 2));
            cp_async16(BsA + idx * 4, Bg + (size_t)r * 32 + kf);
        }
        CP_COMMIT();
    }
    CP_WAIT(1);          // stage 0 resident
    __syncthreads();

    // ---- warp tiling: 2(m) x 4(n); warp tile 64x64 ----
    const int mb = (wid & 1) * 64;
    const int nb = (wid >> 1) * 64;

    const int rA_l = lane & 15;
    const int dkA  = (lane >> 4) << 2;
    const int rB_l = (lane & 7) + ((lane >> 4) << 3);
    const int dkB  = ((lane >> 3) & 1) << 2;

    uint32_t aBase[4], bBase[4];
    int aXc[4], bXc[4];
    #pragma unroll
    for (int mt = 0; mt < 4; mt++) {
        int r = mb + mt * 16 + rA_l;
        aBase[mt] = AsA + r * 512;
        aXc[mt]   = (r & 7) << 2;
    }
    #pragma unroll
    for (int q = 0; q < 4; q++) {
        int r = nb + q * 16 + rB_l;
        bBase[q] = BsA + r * 512;
        bXc[q]   = (r & 7) << 2;
    }

    float acc[4][8][4];
    #pragma unroll
    for (int mt = 0; mt < 4; mt++)
        #pragma unroll
        for (int nt = 0; nt < 8; nt++)
            #pragma unroll
            for (int e = 0; e < 4; e++) acc[mt][nt][e] = 0.0f;

    uint32_t af[2][4][4];   // [buf][mt][reg]
    uint32_t bf[2][8][2];   // [buf][nt][reg]

    #define LOAD_FRAGS(ks, buf)                                               \
        do {                                                                  \
            int kk = (ks) << 3;                                               \
            _Pragma("unroll")                                                 \
            for (int mt = 0; mt < 4; mt++)                                    \
                ldsm_x4(af[buf][mt],                                          \
                        aBase[mt] + ((((kk | dkA) ^ aXc[mt])) << 2));         \
            _Pragma("unroll")                                                 \
            for (int q = 0; q < 4; q++) {                                     \
                uint32_t t[4];                                                \
                ldsm_x4(t, bBase[q] + ((((kk | dkB) ^ bXc[q])) << 2));        \
                bf[buf][q * 2 + 0][0] = t[0];                                 \
                bf[buf][q * 2 + 0][1] = t[1];                                 \
                bf[buf][q * 2 + 1][0] = t[2];                                 \
                bf[buf][q * 2 + 1][1] = t[3];                                 \
            }                                                                 \
        } while (0)

    #define MMA_STEP(buf)                                                     \
        do {                                                                  \
            _Pragma("unroll")                                                 \
            for (int mt = 0; mt < 4; mt++)                                    \
                _Pragma("unroll")                                             \
                for (int nt = 0; nt < 8; nt++)                                \
                    mma_tf32(acc[mt][nt], af[buf][mt], bf[buf][nt]);          \
        } while (0)

    LOAD_FRAGS(0, 0);
    #pragma unroll
    for (int ks = 0; ks < 7; ks++) {
        LOAD_FRAGS(ks + 1, (ks + 1) & 1);
        MMA_STEP(ks & 1);
    }
    MMA_STEP(1);                 // ks = 7
    CP_WAIT(0);                  // stage 1 resident
    __syncthreads();
    LOAD_FRAGS(8, 0);
    #pragma unroll
    for (int ks = 8; ks < 15; ks++) {
        LOAD_FRAGS(ks + 1, (ks + 1) & 1);
        MMA_STEP(ks & 1);
    }
    MMA_STEP(1);                 // ks = 15
    #undef LOAD_FRAGS
    #undef MMA_STEP

    // ---- epilogue: stage -> conflict-free smem -> coalesced STG.128 ----
    __syncthreads();             // everyone done with As/Bs LDSM reads
    float* stg = smem + AS_F + wid * (16 * STG_STRIDE);

    const int cl = 4 * (lane & 15);      // col block within warp tile
    const int rsel = lane >> 4;          // row parity for read phase
    const float4 b2v = *reinterpret_cast<const float4*>(&b2s[nb + cl]);
    const int xw = ((g >> 2) & 1) << 2;  // write xor (rows 4-7,12-15)

    #pragma unroll
    for (int mt = 0; mt < 4; mt++) {
        // write: rows g and g+8, cols nt*8 + 2*tig (+1)
        #pragma unroll
        for (int nt = 0; nt < 8; nt++) {
            int c = (nt * 8 + 2 * tig) ^ xw;
            *reinterpret_cast<float2*>(&stg[g * STG_STRIDE + c]) =
                make_float2(acc[mt][nt][0], acc[mt][nt][1]);
            *reinterpret_cast<float2*>(&stg[(g + 8) * STG_STRIDE + c]) =
                make_float2(acc[mt][nt][2], acc[mt][nt][3]);
        }
        __syncwarp();
        // read pairs of rows; coalesced float4 stores
        #pragma unroll
        for (int rr = 0; rr < 8; rr++) {
            int r = rr * 2 + rsel;
            int xorv = ((r >> 2) & 1) << 2;
            float4 v = *reinterpret_cast<const float4*>(
                &stg[r * STG_STRIDE + (cl ^ xorv)]);
            float a2r = a2s[mb + mt * 16 + r];
            float4 o;
            o.x = -fast_sqrt(fmaxf(fmaf(-2.0f, v.x, a2r + b2v.x), 0.0f));
            o.y = -fast_sqrt(fmaxf(fmaf(-2.0f, v.y, a2r + b2v.y), 0.0f));
            o.z = -fast_sqrt(fmaxf(fmaf(-2.0f, v.z, a2r + b2v.z), 0.0f));
            o.w = -fast_sqrt(fmaxf(fmaf(-2.0f, v.w, a2r + b2v.w), 0.0f));
            *reinterpret_cast<float4*>(
                &out[(size_t)(row0 + mb + mt * 16 + r) * M + (col0 + nb + cl)])
                = o;
        }
        __syncwarp();
    }
}

extern "C" void kernel_launch(void* const* d_in, const int* in_sizes, int n_in,
                              void* d_out, int out_size) {
    const float* A = (const float*)d_in[0];   // z_anc [N,128]
    const float* B = (const float*)d_in[1];   // z_pos_neg [M,128]
    float* out = (float*)d_out;

    const int N = in_sizes[0] / DDIM;
    const int M = in_sizes[1] / DDIM;

    // First call is the (non-captured) correctness run; capture-safe.
    static bool attr_ok = [] {
        cudaFuncSetAttribute(dist_mma_kernel,
                             cudaFuncAttributeMaxDynamicSharedMemorySize,
                             SMEM_BYTES);
        return true;
    }();
    (void)attr_ok;

    int totalRows = N + M;
    norms_kernel<<<(totalRows + 7) / 8, 256>>>(A, B, N, M);

    dim3 grid(M / TN, N / TM);
    dist_mma_kernel<<<grid, 256, SMEM_BYTES>>>(A, B, out, N, M);
}

// round 10
// speedup vs baseline: 3.9304x; 1.2158x over previous
#include <cuda_runtime.h>
#include <math.h>
#include <stdint.h>

// out[n][m] = -sqrt(max(||a_n||^2 + ||b_m||^2 - 2 <a_n,b_m>, 0))
// Round 10: round-9 design with the stage-index bug fixed (the final
// K-chunk lives in ring stage 0; round 9 erroneously indexed "stage 3",
// reading 32KB past the smem allocation).
//  - CTA 128x128, 3-stage cp.async ring (K-chunks of 32) -> 96KB, 2 CTAs/SM.
//  - 8 warps (4m x 2n), warp tile 32x64, ldmatrix fragment feed.
//  - Epilogue staged through conflict-free smem -> coalesced STG.128.

#define DDIM 128
#define TM   128
#define TN   128

__device__ float g_a2[8192];
__device__ float g_b2[8192];

__global__ void norms_kernel(const float* __restrict__ A,
                             const float* __restrict__ B, int N, int M) {
    int row  = blockIdx.x * 8 + (threadIdx.x >> 5);
    int lane = threadIdx.x & 31;
    const float* src;
    float* dst;
    if (row < N) { src = A + (size_t)row * DDIM; dst = g_a2 + row; }
    else {
        int r = row - N;
        if (r >= M) return;
        src = B + (size_t)r * DDIM; dst = g_b2 + r;
    }
    float4 v = reinterpret_cast<const float4*>(src)[lane];
    float s = v.x * v.x + v.y * v.y + v.z * v.z + v.w * v.w;
    #pragma unroll
    for (int o = 16; o; o >>= 1) s += __shfl_xor_sync(0xffffffffu, s, o);
    if (lane == 0) *dst = s;
}

__device__ __forceinline__ uint32_t smem_u32(const void* p) {
    uint32_t a;
    asm("{ .reg .u64 t; cvta.to.shared.u64 t, %1; cvt.u32.u64 %0, t; }"
        : "=r"(a) : "l"(p));
    return a;
}
__device__ __forceinline__ void mma_tf32(float* c, const uint32_t* a,
                                         const uint32_t* b) {
    asm volatile(
        "mma.sync.aligned.m16n8k8.row.col.f32.tf32.tf32.f32 "
        "{%0,%1,%2,%3}, {%4,%5,%6,%7}, {%8,%9}, {%0,%1,%2,%3};"
        : "+f"(c[0]), "+f"(c[1]), "+f"(c[2]), "+f"(c[3])
        : "r"(a[0]), "r"(a[1]), "r"(a[2]), "r"(a[3]), "r"(b[0]), "r"(b[1]));
}
__device__ __forceinline__ void ldsm_x4(uint32_t* r, uint32_t addr) {
    asm volatile(
        "ldmatrix.sync.aligned.m8n8.x4.shared.b16 {%0,%1,%2,%3}, [%4];"
        : "=r"(r[0]), "=r"(r[1]), "=r"(r[2]), "=r"(r[3]) : "r"(addr));
}
__device__ __forceinline__ void cp_async16(uint32_t dst, const void* src) {
    asm volatile("cp.async.cg.shared.global [%0], [%1], 16;"
                 :: "r"(dst), "l"(src));
}
#define CP_COMMIT() asm volatile("cp.async.commit_group;" ::: "memory")
#define CP_WAIT(n)  asm volatile("cp.async.wait_group %0;" :: "n"(n) : "memory")

// FFMA-only sqrt: magic rsqrt + 2 Newton steps; 0 -> 0 (no NaN).
__device__ __forceinline__ float fast_sqrt(float x) {
    float y = __int_as_float(0x5f3759df - (__float_as_int(x) >> 1));
    float h = 0.5f * x;
    y = y * (1.5f - h * y * y);
    y = y * (1.5f - h * y * y);
    return x * y;
}

// Ring: 3 stages x 8192 floats (A 128x32 at +0, B 128x32 at +4096 floats).
// Then a2s[128], b2s[128]. Epilogue staging reuses the ring.
#define RING_F      8192
#define A2S_F       24576
#define B2S_F       24704
#define SMEM_FLOATS 24832
#define SMEM_BYTES  (SMEM_FLOATS * 4)
#define STG_STRIDE  72

__global__ __launch_bounds__(256, 2)
void dist_mma_kernel(const float* __restrict__ A, const float* __restrict__ B,
                     float* __restrict__ out, int N, int M) {
    extern __shared__ float smem[];
    float* a2s = smem + A2S_F;
    float* b2s = smem + B2S_F;

    const int tid  = threadIdx.x;
    const int wid  = tid >> 5;      // 0..7
    const int lane = tid & 31;
    const int g    = lane >> 2;
    const int tig  = lane & 3;
    const int row0 = blockIdx.y * TM;
    const int col0 = blockIdx.x * TN;

    const uint32_t SA = smem_u32(smem);

    if (tid < 128)      a2s[tid] = g_a2[row0 + tid];
    else                b2s[tid - 128] = g_b2[col0 + tid - 128];

    // ---- cp.async: chunk c (K cols c*32..c*32+31) -> ring stage s ----
    const float4* Ag = reinterpret_cast<const float4*>(A + (size_t)row0 * DDIM);
    const float4* Bg = reinterpret_cast<const float4*>(B + (size_t)col0 * DDIM);
    const int rL = tid >> 3;        // base row (0..31), +i*32
    const int qL = tid & 7;         // float4 within 32-float chunk row
    #define ISSUE_CHUNK(c, s)                                                 \
        do {                                                                  \
            uint32_t aDst = SA + (uint32_t)((s) * RING_F) * 4;                \
            uint32_t bDst = aDst + 4096 * 4;                                  \
            _Pragma("unroll")                                                 \
            for (int i = 0; i < 4; i++) {                                     \
                int r = rL + i * 32;                                          \
                int idx = r * 32 + ((qL * 4) ^ ((r & 7) << 2));               \
                cp_async16(aDst + idx * 4, Ag + (size_t)r * 32 + (c) * 8 + qL);\
                cp_async16(bDst + idx * 4, Bg + (size_t)r * 32 + (c) * 8 + qL);\
            }                                                                 \
            CP_COMMIT();                                                      \
        } while (0)

    ISSUE_CHUNK(0, 0);
    ISSUE_CHUNK(1, 1);
    ISSUE_CHUNK(2, 2);

    // ---- warp tiling: 4(m) x 2(n); warp tile 32x64 ----
    const int mb = (wid & 3) * 32;
    const int nb = (wid >> 2) * 64;

    const int rA_l = lane & 15;
    const int dkA  = (lane >> 4) << 2;
    const int rB_l = (lane & 7) + ((lane >> 4) << 3);
    const int dkB  = ((lane >> 3) & 1) << 2;

    uint32_t aRowOff[2], bRowOff[4];
    int aXc[2], bXc[4];
    #pragma unroll
    for (int mt = 0; mt < 2; mt++) {
        int r = mb + mt * 16 + rA_l;
        aRowOff[mt] = (uint32_t)r * 128;
        aXc[mt]     = (r & 7) << 2;
    }
    #pragma unroll
    for (int q = 0; q < 4; q++) {
        int r = nb + q * 16 + rB_l;
        bRowOff[q] = 4096 * 4 + (uint32_t)r * 128;
        bXc[q]     = (r & 7) << 2;
    }

    float acc[2][8][4];
    #pragma unroll
    for (int mt = 0; mt < 2; mt++)
        #pragma unroll
        for (int nt = 0; nt < 8; nt++)
            #pragma unroll
            for (int e = 0; e < 4; e++) acc[mt][nt][e] = 0.0f;

    uint32_t af[2][4];
    uint32_t bf[8][2];

    // s = RING STAGE index (0..2), independent of chunk number.
    #define CHUNK_MMA(s)                                                      \
        do {                                                                  \
            uint32_t stBase = SA + (uint32_t)((s) * RING_F) * 4;              \
            _Pragma("unroll")                                                 \
            for (int ks = 0; ks < 4; ks++) {                                  \
                int kk = ks << 3;                                             \
                _Pragma("unroll")                                             \
                for (int mt = 0; mt < 2; mt++)                                \
                    ldsm_x4(af[mt], stBase + aRowOff[mt] +                    \
                            ((((kk | dkA) ^ aXc[mt])) << 2));                 \
                _Pragma("unroll")                                             \
                for (int q = 0; q < 4; q++) {                                 \
                    uint32_t t[4];                                            \
                    ldsm_x4(t, stBase + bRowOff[q] +                          \
                            ((((kk | dkB) ^ bXc[q])) << 2));                  \
                    bf[q * 2 + 0][0] = t[0];                                  \
                    bf[q * 2 + 0][1] = t[1];                                  \
                    bf[q * 2 + 1][0] = t[2];                                  \
                    bf[q * 2 + 1][1] = t[3];                                  \
                }                                                             \
                _Pragma("unroll")                                             \
                for (int mt = 0; mt < 2; mt++)                                \
                    _Pragma("unroll")                                         \
                    for (int nt = 0; nt < 8; nt++)                            \
                        mma_tf32(acc[mt][nt], af[mt], bf[nt]);                \
            }                                                                 \
        } while (0)

    CP_WAIT(2); __syncthreads();   // chunk 0 resident (stage 0)
    CHUNK_MMA(0);
    __syncthreads();               // all warps done reading stage 0
    ISSUE_CHUNK(3, 0);             // chunk 3 -> stage 0
    CP_WAIT(2); __syncthreads();   // chunk 1 resident (stage 1)
    CHUNK_MMA(1);
    CP_WAIT(1); __syncthreads();   // chunk 2 resident (stage 2)
    CHUNK_MMA(2);
    CP_WAIT(0); __syncthreads();   // chunk 3 resident (stage 0)
    CHUNK_MMA(0);                  // <-- stage 0, NOT "3" (round-9 bug)
    #undef CHUNK_MMA
    #undef ISSUE_CHUNK

    // ---- epilogue: stage -> conflict-free smem -> coalesced STG.128 ----
    __syncthreads();               // done with ring; reuse as staging
    float* stg = smem + wid * (16 * STG_STRIDE);

    const int cl   = 4 * (lane & 15);
    const int rsel = lane >> 4;
    const float4 b2v = *reinterpret_cast<const float4*>(&b2s[nb + cl]);
    const int xw = ((g >> 2) & 1) << 2;

    #pragma unroll
    for (int mt = 0; mt < 2; mt++) {
        #pragma unroll
        for (int nt = 0; nt < 8; nt++) {
            int c = (nt * 8 + 2 * tig) ^ xw;
            *reinterpret_cast<float2*>(&stg[g * STG_STRIDE + c]) =
                make_float2(acc[mt][nt][0], acc[mt][nt][1]);
            *reinterpret_cast<float2*>(&stg[(g + 8) * STG_STRIDE + c]) =
                make_float2(acc[mt][nt][2], acc[mt][nt][3]);
        }
        __syncwarp();
        #pragma unroll
        for (int rr = 0; rr < 8; rr++) {
            int r = rr * 2 + rsel;
            int xorv = ((r >> 2) & 1) << 2;
            float4 v = *reinterpret_cast<const float4*>(
                &stg[r * STG_STRIDE + (cl ^ xorv)]);
            float a2r = a2s[mb + mt * 16 + r];
            float4 o;
            o.x = -fast_sqrt(fmaxf(fmaf(-2.0f, v.x, a2r + b2v.x), 0.0f));
            o.y = -fast_sqrt(fmaxf(fmaf(-2.0f, v.y, a2r + b2v.y), 0.0f));
            o.z = -fast_sqrt(fmaxf(fmaf(-2.0f, v.z, a2r + b2v.z), 0.0f));
            o.w = -fast_sqrt(fmaxf(fmaf(-2.0f, v.w, a2r + b2v.w), 0.0f));
            *reinterpret_cast<float4*>(
                &out[(size_t)(row0 + mb + mt * 16 + r) * M + (col0 + nb + cl)])
                = o;
        }
        __syncwarp();
    }
}

extern "C" void kernel_launch(void* const* d_in, const int* in_sizes, int n_in,
                              void* d_out, int out_size) {
    const float* A = (const float*)d_in[0];   // z_anc [N,128]
    const float* B = (const float*)d_in[1];   // z_pos_neg [M,128]
    float* out = (float*)d_out;

    const int N = in_sizes[0] / DDIM;
    const int M = in_sizes[1] / DDIM;

    // First call is the (non-captured) correctness run; capture-safe.
    static bool attr_ok = [] {
        cudaFuncSetAttribute(dist_mma_kernel,
                             cudaFuncAttributeMaxDynamicSharedMemorySize,
                             SMEM_BYTES);
        return true;
    }();
    (void)attr_ok;

    int totalRows = N + M;
    norms_kernel<<<(totalRows + 7) / 8, 256>>>(A, B, N, M);

    dim3 grid(M / TN, N / TM);
    dist_mma_kernel<<<grid, 256, SMEM_BYTES>>>(A, B, out, N, M);
}